// round 1
// baseline (speedup 1.0000x reference)
#include <cuda_runtime.h>
#include <math.h>

#define NB 8
#define NC 12
#define NNtok 785
#define NS 784
#define NH 28
#define ND 768
#define KHID 512
#define PNUM 84
#define SCL 0.7f

// ---------------- device scratch (no allocations allowed) ----------------
__device__ float g_ns[NB * NC * NS];     // new_score
__device__ float g_selmask[NB * NC * NS];// selected flags (1.0/0.0)
__device__ float g_u1p[NB * KHID];       // relu(u1)
__device__ float g_u1m[NB * KHID];       // relu(-u1)
__device__ float g_scal[NB * 4];         // pw[anchor], c+, c-
__device__ float g_struct[NB * ND];      // struct row at anchor
__device__ int   g_patch[NB * NS];       // patch indices by rank (only first seln used)

// ---------------- Kernel A: per (b,c) top-84 selection ----------------
__global__ __launch_bounds__(256) void kTopSel(const float* __restrict__ x)
{
    __shared__ float    sc[NS];
    __shared__ unsigned su[NS];
    __shared__ int      red[8];
    __shared__ int      s_g;
    const int bc  = blockIdx.x;
    const int tid = threadIdx.x;
    const float* row = x + (long long)bc * NNtok * NNtok + 1;  // x[b,c,0,1:]

    for (int i = tid; i < NS; i += 256) {
        float v = row[i];
        sc[i] = v;
        unsigned ub = __float_as_uint(v);
        su[i] = (ub & 0x80000000u) ? ~ub : (ub | 0x80000000u);  // order-preserving key
    }
    __syncthreads();

    // binary search: T = 84th largest key (max T with count(>=T) >= 84)
    unsigned lo = 0u, hi = 0xFFFFFFFFu;
    while (lo < hi) {
        unsigned mid = lo + ((hi - lo) >> 1) + 1u;
        int c = 0;
        for (int i = tid; i < NS; i += 256) c += (su[i] >= mid) ? 1 : 0;
        for (int o = 16; o; o >>= 1) c += __shfl_xor_sync(0xFFFFFFFFu, c, o);
        if ((tid & 31) == 0) red[tid >> 5] = c;
        __syncthreads();
        int tot = 0;
        #pragma unroll
        for (int w = 0; w < 8; w++) tot += red[w];
        if (tot >= PNUM) lo = mid; else hi = mid - 1u;
        __syncthreads();
    }
    const unsigned T = lo;

    int cg = 0;
    for (int i = tid; i < NS; i += 256) cg += (su[i] > T) ? 1 : 0;
    for (int o = 16; o; o >>= 1) cg += __shfl_xor_sync(0xFFFFFFFFu, cg, o);
    if ((tid & 31) == 0) red[tid >> 5] = cg;
    __syncthreads();
    if (tid == 0) { int t = 0; for (int w = 0; w < 8; w++) t += red[w]; s_g = t; }
    __syncthreads();
    const int need = PNUM - s_g;  // ties taken by ascending index (matches lax.top_k)

    for (int i = tid; i < NS; i += 256) {
        unsigned u = su[i];
        bool sel;
        if (u > T) sel = true;
        else if (u == T) {
            int e = 0;
            for (int j = 0; j < i; j++) e += (su[j] == T) ? 1 : 0;
            sel = (e < need);
        } else sel = false;
        float v = sc[i];
        g_ns[bc * NS + i]      = sel ? v : v * SCL;
        g_selmask[bc * NS + i] = sel ? 1.0f : 0.0f;
    }
}

// ---------------- Kernel B1: per-b stats, anchor, u1 ----------------
__global__ __launch_bounds__(256) void kStats(const float* __restrict__ w1)
{
    __shared__ float msh[NS];
    __shared__ float redf[8], redf2[8], redf3[8], redf4[8];
    __shared__ int   redi[8];
    __shared__ float s_mean, s_w0, s_w1;
    __shared__ int   s_anchor;
    const int b = blockIdx.x, tid = threadIdx.x;
    const int warp = tid >> 5, lane = tid & 31;

    float psum = 0.f;
    for (int s = tid; s < NS; s += 256) {
        float m = 0.f;
        #pragma unroll
        for (int c = 0; c < NC; c++) m += g_ns[(b * NC + c) * NS + s];
        msh[s] = m;
        psum += m;
    }
    for (int o = 16; o; o >>= 1) psum += __shfl_xor_sync(0xFFFFFFFFu, psum, o);
    if (lane == 0) redf[warp] = psum;
    __syncthreads();
    if (tid == 0) {
        float t = 0.f; for (int w = 0; w < 8; w++) t += redf[w];
        s_mean = t / (float)NS;
    }
    __syncthreads();
    const float mean = s_mean;

    // argmax of binary*m/C with first-index tie-break
    float bv = -1e30f; int bi = NS;
    for (int s = tid; s < NS; s += 256) {
        float m = msh[s];
        float v = (m > mean) ? m * (1.0f / NC) : 0.0f;
        if (v > bv || (v == bv && s < bi)) { bv = v; bi = s; }
    }
    for (int o = 16; o; o >>= 1) {
        float ov = __shfl_xor_sync(0xFFFFFFFFu, bv, o);
        int   oi = __shfl_xor_sync(0xFFFFFFFFu, bi, o);
        if (ov > bv || (ov == bv && oi < bi)) { bv = ov; bi = oi; }
    }
    if (lane == 0) { redf[warp] = bv; redi[warp] = bi; }
    __syncthreads();
    if (tid == 0) {
        float v = redf[0]; int i = redi[0];
        for (int w = 1; w < 8; w++)
            if (redf[w] > v || (redf[w] == v && redi[w] < i)) { v = redf[w]; i = redi[w]; }
        s_anchor = i;
    }
    __syncthreads();
    const int anchor = s_anchor;
    const float ai = (float)(anchor / NH), aj = (float)(anchor % NH);

    float w0 = 0.f, w1s = 0.f, cp = 0.f, cm = 0.f;
    for (int s = tid; s < NS; s += 256) {
        float p   = msh[s] * (1.0f / NC);
        float rc0 = ((float)(s / NH) - ai) / (float)NH;
        float rc1 = ((float)(s % NH) - aj) / (float)NH;
        float dist = sqrtf(rc0 * rc0 + rc1 * rc1);
        float ang  = (atan2f(rc1, rc0) * 0.3183098861837907f + 1.0f) * 0.5f;
        w0  += p * dist;
        w1s += p * ang;
        if (p > 0.f) cp += p * p; else if (p < 0.f) cm += p * p;
    }
    for (int o = 16; o; o >>= 1) {
        w0  += __shfl_xor_sync(0xFFFFFFFFu, w0,  o);
        w1s += __shfl_xor_sync(0xFFFFFFFFu, w1s, o);
        cp  += __shfl_xor_sync(0xFFFFFFFFu, cp,  o);
        cm  += __shfl_xor_sync(0xFFFFFFFFu, cm,  o);
    }
    if (lane == 0) { redf[warp] = w0; redf2[warp] = w1s; redf3[warp] = cp; redf4[warp] = cm; }
    __syncthreads();
    if (tid == 0) {
        float a = 0, bb = 0, c = 0, d = 0;
        for (int w = 0; w < 8; w++) { a += redf[w]; bb += redf2[w]; c += redf3[w]; d += redf4[w]; }
        s_w0 = a; s_w1 = bb;
        g_scal[b * 4 + 0] = msh[anchor] * (1.0f / NC);
        g_scal[b * 4 + 1] = c;
        g_scal[b * 4 + 2] = d;
    }
    __syncthreads();
    const float W0 = s_w0, W1v = s_w1;
    for (int k = tid; k < KHID; k += 256) {
        float u = W0 * w1[k] + W1v * w1[KHID + k];
        g_u1p[b * KHID + k] = fmaxf(u, 0.f);
        g_u1m[b * KHID + k] = fmaxf(-u, 0.f);
    }
}

// ---------------- Kernel B2: struct row at anchor = leaky(pw_a*(c+ a+ - c- a-)) ----
__global__ __launch_bounds__(256) void kStruct(const float* __restrict__ w2)
{
    __shared__ float up[KHID], um[KHID];
    const int b = blockIdx.x / 3;
    const int j = (blockIdx.x % 3) * 256 + threadIdx.x;
    for (int k = threadIdx.x; k < KHID; k += 256) {
        up[k] = g_u1p[b * KHID + k];
        um[k] = g_u1m[b * KHID + k];
    }
    __syncthreads();
    float ap = 0.f, am = 0.f;
    for (int k = 0; k < KHID; k++) {
        float w = w2[k * ND + j];
        ap += up[k] * w;
        am += um[k] * w;
    }
    const float pa = g_scal[b * 4 + 0], cp = g_scal[b * 4 + 1], cm = g_scal[b * 4 + 2];
    float val = pa * (cp * ap - cm * am);
    g_struct[b * ND + j] = val > 0.f ? val : 0.2f * val;
}

// ---------------- Kernel C: count conv + stable descending ranks ----------------
__global__ __launch_bounds__(256) void kCount(const int* __restrict__ selnum)
{
    __shared__ int c0[NS];
    __shared__ int cc[NS];
    __shared__ int hist[256];
    __shared__ int sg[256];
    const int b = blockIdx.x, tid = threadIdx.x;

    for (int s = tid; s < NS; s += 256) {
        float t = 0.f;
        #pragma unroll
        for (int c = 0; c < NC; c++) t += g_selmask[(b * NC + c) * NS + s];
        c0[s] = (int)(t + 0.5f);
    }
    hist[tid] = 0;
    __syncthreads();

    for (int s = tid; s < NS; s += 256) {
        int i = s / NH, j = s % NH;
        int acc = 0;
        #pragma unroll
        for (int di = -1; di <= 1; di++)
            #pragma unroll
            for (int dj = -1; dj <= 1; dj++) {
                int ii = i + di, jj = j + dj;
                if (ii >= 0 && ii < NH && jj >= 0 && jj < NH) {
                    int w = (2 - abs(di)) * (2 - abs(dj));  // [[1,2,1],[2,4,2],[1,2,1]]
                    acc += w * c0[ii * NH + jj];
                }
            }
        cc[s] = acc;                       // max 192 < 256
        atomicAdd(&hist[acc], 1);
    }
    __syncthreads();
    {   // sg[v] = #elements strictly greater than v
        int g = 0;
        for (int w = tid + 1; w < 256; w++) g += hist[w];
        sg[tid] = g;
    }
    __syncthreads();
    const int seln = *selnum;
    for (int i = tid; i < NS; i += 256) {
        int v = cc[i];
        int g = sg[v];
        if (g < seln) {
            int e = 0;
            for (int j = 0; j < i; j++) e += (cc[j] == v) ? 1 : 0;
            int r = g + e;                 // stable: ties by ascending index
            if (r < seln) g_patch[b * NS + r] = i + 1;
        }
    }
}

// ---------------- Kernel D: hs = hidden_states; row0 += struct[anchor] ----------
#define TOT4 (NB * NNtok * ND / 4)
__global__ __launch_bounds__(256) void kCopy(const float4* __restrict__ hin,
                                             float4* __restrict__ hout)
{
    int i4 = blockIdx.x * 256 + threadIdx.x;
    if (i4 >= TOT4) return;
    float4 v = hin[i4];
    int row = i4 / (ND / 4);
    int n = row % NNtok;
    if (n == 0) {
        int b = row / NNtok;
        int d = (i4 % (ND / 4)) * 4;
        const float* st = &g_struct[b * ND + d];
        v.x += st[0]; v.y += st[1]; v.z += st[2]; v.w += st[3];
    }
    hout[i4] = v;
}

// ---------------- Kernel E: selected = hidden_states[b, patch_idx] (rows >= 1) ----
__global__ __launch_bounds__(256) void kGather(const float4* __restrict__ hin,
                                               float4* __restrict__ sout,
                                               int seln, int tot4)
{
    int i4 = blockIdx.x * 256 + threadIdx.x;
    if (i4 >= tot4) return;
    int row = i4 / (ND / 4);       // b*seln + q
    int d4  = i4 % (ND / 4);
    int b = row / seln;
    int q = row % seln;
    int p = g_patch[b * NS + q];   // in [1, 784] -> unmodified hs rows == input rows
    sout[i4] = hin[(long long)(b * NNtok + p) * (ND / 4) + d4];
}

// ---------------- launch ----------------
extern "C" void kernel_launch(void* const* d_in, const int* in_sizes, int n_in,
                              void* d_out, int out_size)
{
    const float* hs = (const float*)d_in[0];
    const float* x  = (const float*)d_in[1];
    const float* w1 = (const float*)d_in[2];
    const float* w2 = (const float*)d_in[3];
    const int* seln_dev = (const int*)d_in[4];

    float* out_hs = (float*)d_out;
    const int hs_elems = NB * NNtok * ND;
    int sel_elems = out_size - hs_elems;
    int seln = sel_elems / (NB * ND);
    if (seln < 1) seln = 1;
    float* out_sel = out_hs + hs_elems;

    kTopSel<<<NB * NC, 256>>>(x);
    kStats<<<NB, 256>>>(w1);
    kStruct<<<NB * 3, 256>>>(w2);
    kCount<<<NB, 256>>>(seln_dev);
    kCopy<<<(TOT4 + 255) / 256, 256>>>((const float4*)hs, (float4*)out_hs);
    int tot4 = NB * seln * (ND / 4);
    kGather<<<(tot4 + 255) / 256, 256>>>((const float4*)hs, (float4*)out_sel, seln, tot4);
}

// round 2
// speedup vs baseline: 1.5268x; 1.5268x over previous
#include <cuda_runtime.h>
#include <math.h>

#define NB 8
#define NC 12
#define NNtok 785
#define NS 784
#define NH 28
#define ND 768
#define KHID 512
#define PNUM 84
#define SCL 0.7f

// ---------------- device scratch ----------------
__device__ float         g_ns[NB * NC * NS];   // new_score
__device__ unsigned char g_sel[NB * NC * NS];  // selected flag per (b,c,s)
__device__ float         g_u1p[NB * KHID];     // relu(u1)
__device__ float         g_u1m[NB * KHID];     // relu(-u1)
__device__ float         g_scal[NB * 4];       // pw[anchor], c+, c-
__device__ float         g_struct[NB * ND];    // struct row at anchor
__device__ int           g_patch[NB * NS];     // patch idx by rank (first seln used)

// ================= Kernel A: per (b,c) top-84 via 4-pass radix select ==========
__global__ __launch_bounds__(256) void kTopSel(const float* __restrict__ x)
{
    __shared__ float    sc[NS];
    __shared__ unsigned su[NS];
    __shared__ int      hist[256];
    __shared__ unsigned s_pref;
    __shared__ int      s_rem;
    const int bc = blockIdx.x, tid = threadIdx.x;
    const float* row = x + (long long)bc * NNtok * NNtok + 1;   // x[b,c,0,1:]

    for (int i = tid; i < NS; i += 256) {
        float v = row[i];
        sc[i] = v;
        unsigned ub = __float_as_uint(v);
        su[i] = (ub & 0x80000000u) ? ~ub : (ub | 0x80000000u);  // order-preserving key
    }
    if (tid == 0) { s_pref = 0u; s_rem = PNUM; }
    __syncthreads();

    #pragma unroll
    for (int pass = 0; pass < 4; pass++) {
        const int shift = 24 - 8 * pass;
        const unsigned mask_hi = (pass == 0) ? 0u : (0xFFFFFFFFu << (shift + 8));
        hist[tid] = 0;
        __syncthreads();
        const unsigned pref = s_pref;
        const int rem = s_rem;
        for (int i = tid; i < NS; i += 256) {
            unsigned u = su[i];
            if ((u & mask_hi) == pref) atomicAdd(&hist[(u >> shift) & 0xFFu], 1);
        }
        __syncthreads();
        // exactly one tid satisfies: sfx_gt < rem <= sfx_gt + hist[tid]
        int sfx = 0;
        for (int w = tid + 1; w < 256; w++) sfx += hist[w];
        if (sfx < rem && sfx + hist[tid] >= rem) {
            s_pref = pref | ((unsigned)tid << shift);
            s_rem  = rem - sfx;
        }
        __syncthreads();
    }
    const unsigned T = s_pref;   // exact 84th-largest key
    const int need  = s_rem;     // # of T-ties to take (ascending index, = lax.top_k)

    for (int i = tid; i < NS; i += 256) {
        unsigned u = su[i];
        bool sel;
        if (u > T) sel = true;
        else if (u == T) {
            int e = 0;
            for (int j = 0; j < i; j++) e += (su[j] == T) ? 1 : 0;
            sel = (e < need);
        } else sel = false;
        g_ns[bc * NS + i]  = sel ? sc[i] : sc[i] * SCL;
        g_sel[bc * NS + i] = sel ? (unsigned char)1 : (unsigned char)0;
    }
}

// ===== Kernel B: per-b stats + anchor + u1 + count-conv + stable ranks =========
__global__ __launch_bounds__(256) void kPerB(const float* __restrict__ w1, int seln)
{
    __shared__ float msh[NS];
    __shared__ int   c0[NS];
    __shared__ int   cc[NS];
    __shared__ int   whist[8][256];
    __shared__ int   htot[256];
    __shared__ int   sfx[256];
    __shared__ float redf[8], redf2[8], redf3[8], redf4[8];
    __shared__ int   redi[8];
    __shared__ float s_mean, s_w0, s_w1;
    __shared__ int   s_anchor;
    const int b = blockIdx.x, tid = threadIdx.x;
    const int warp = tid >> 5, lane = tid & 31;

    // ---- m[s] = sum_c new_score; mean ----
    float psum = 0.f;
    for (int s = tid; s < NS; s += 256) {
        float m = 0.f;
        #pragma unroll
        for (int c = 0; c < NC; c++) m += g_ns[(b * NC + c) * NS + s];
        msh[s] = m;
        psum += m;
    }
    for (int o = 16; o; o >>= 1) psum += __shfl_xor_sync(0xFFFFFFFFu, psum, o);
    if (lane == 0) redf[warp] = psum;
    __syncthreads();
    if (tid == 0) {
        float t = 0.f; for (int w = 0; w < 8; w++) t += redf[w];
        s_mean = t / (float)NS;
    }
    __syncthreads();
    const float mean = s_mean;

    // ---- anchor = argmax(binary * m / C), first-index tie-break ----
    float bv = -1e30f; int bi = NS;
    for (int s = tid; s < NS; s += 256) {
        float m = msh[s];
        float v = (m > mean) ? m * (1.0f / NC) : 0.0f;
        if (v > bv || (v == bv && s < bi)) { bv = v; bi = s; }
    }
    for (int o = 16; o; o >>= 1) {
        float ov = __shfl_xor_sync(0xFFFFFFFFu, bv, o);
        int   oi = __shfl_xor_sync(0xFFFFFFFFu, bi, o);
        if (ov > bv || (ov == bv && oi < bi)) { bv = ov; bi = oi; }
    }
    if (lane == 0) { redf[warp] = bv; redi[warp] = bi; }
    __syncthreads();
    if (tid == 0) {
        float v = redf[0]; int i = redi[0];
        for (int w = 1; w < 8; w++)
            if (redf[w] > v || (redf[w] == v && redi[w] < i)) { v = redf[w]; i = redi[w]; }
        s_anchor = i;
    }
    __syncthreads();
    const int anchor = s_anchor;
    const float ai = (float)(anchor / NH), aj = (float)(anchor % NH);

    // ---- w0 = sum pw*dist, w1 = sum pw*ang, c+ = sum_{pw>0} pw^2, c- likewise ----
    float w0 = 0.f, w1s = 0.f, cpv = 0.f, cmv = 0.f;
    for (int s = tid; s < NS; s += 256) {
        float p   = msh[s] * (1.0f / NC);
        float rc0 = ((float)(s / NH) - ai) / (float)NH;
        float rc1 = ((float)(s % NH) - aj) / (float)NH;
        float dist = sqrtf(rc0 * rc0 + rc1 * rc1);
        float ang  = (atan2f(rc1, rc0) * 0.3183098861837907f + 1.0f) * 0.5f;
        w0  += p * dist;
        w1s += p * ang;
        if (p > 0.f) cpv += p * p; else if (p < 0.f) cmv += p * p;
    }
    for (int o = 16; o; o >>= 1) {
        w0  += __shfl_xor_sync(0xFFFFFFFFu, w0,  o);
        w1s += __shfl_xor_sync(0xFFFFFFFFu, w1s, o);
        cpv += __shfl_xor_sync(0xFFFFFFFFu, cpv, o);
        cmv += __shfl_xor_sync(0xFFFFFFFFu, cmv, o);
    }
    if (lane == 0) { redf[warp] = w0; redf2[warp] = w1s; redf3[warp] = cpv; redf4[warp] = cmv; }
    __syncthreads();
    if (tid == 0) {
        float a = 0, bb = 0, c = 0, d = 0;
        for (int w = 0; w < 8; w++) { a += redf[w]; bb += redf2[w]; c += redf3[w]; d += redf4[w]; }
        s_w0 = a; s_w1 = bb;
        g_scal[b * 4 + 0] = msh[anchor] * (1.0f / NC);
        g_scal[b * 4 + 1] = c;
        g_scal[b * 4 + 2] = d;
    }
    __syncthreads();

    // ---- u1 halves ----
    {
        const float W0 = s_w0, W1v = s_w1;
        for (int k = tid; k < KHID; k += 256) {
            float u = W0 * w1[k] + W1v * w1[KHID + k];
            g_u1p[b * KHID + k] = fmaxf(u, 0.f);
            g_u1m[b * KHID + k] = fmaxf(-u, 0.f);
        }
    }

    // ---- count = sum_c selmask ----
    for (int s = tid; s < NS; s += 256) {
        int t = 0;
        #pragma unroll
        for (int c = 0; c < NC; c++) t += (int)g_sel[(b * NC + c) * NS + s];
        c0[s] = t;
    }
    #pragma unroll
    for (int r = 0; r < 8; r++) whist[r][tid] = 0;
    __syncthreads();

    // ---- 3x3 conv + per-warp (98-elem chunk) value histograms ----
    {
        const int base = warp * 98;                 // 8*98 = 784 exactly
        for (int o = lane; o < 98; o += 32) {
            int s = base + o;
            int i0 = s / NH, j0 = s % NH;
            int acc = 0;
            #pragma unroll
            for (int di = -1; di <= 1; di++)
                #pragma unroll
                for (int dj = -1; dj <= 1; dj++) {
                    int ii = i0 + di, jj = j0 + dj;
                    if (ii >= 0 && ii < NH && jj >= 0 && jj < NH)
                        acc += (2 - abs(di)) * (2 - abs(dj)) * c0[ii * NH + jj];
                }
            cc[s] = acc;                            // max 192 < 256
            atomicAdd(&whist[warp][acc], 1);
        }
    }
    __syncthreads();
    {
        int t = 0;
        #pragma unroll
        for (int r = 0; r < 8; r++) t += whist[r][tid];
        htot[tid] = t;
    }
    __syncthreads();
    {
        int g = 0;
        for (int v = tid + 1; v < 256; v++) g += htot[v];   // # strictly greater
        sfx[tid] = g;
    }
    __syncthreads();

    // ---- stable descending rank, write patch indices ----
    {
        const int base = warp * 98;
        for (int o = lane; o < 98; o += 32) {
            int i = base + o;
            int v = cc[i];
            int g = sfx[v];
            if (g < seln) {
                int e = 0;
                #pragma unroll
                for (int r = 0; r < 8; r++) if (r < warp) e += whist[r][v];
                for (int j = base; j < i; j++) e += (cc[j] == v) ? 1 : 0;
                int rk = g + e;                     // ties by ascending index (stable)
                if (rk < seln) g_patch[b * NS + rk] = i + 1;
            }
        }
    }
}

// ========= Kernel C: struct row at anchor = leaky(pw_a*(c+ a+ - c- a-)) ========
// grid = NB*12 blocks; block (b, jg) computes 64 outputs, K split 4-way.
__global__ __launch_bounds__(256) void kStruct(const float* __restrict__ w2)
{
    __shared__ float up[KHID], um[KHID];
    __shared__ float sap[4][64], sam[4][64];
    const int b  = blockIdx.x / 12;
    const int j0 = (blockIdx.x % 12) * 64;
    const int tid = threadIdx.x;
    for (int k = tid; k < KHID; k += 256) {
        up[k] = g_u1p[b * KHID + k];
        um[k] = g_u1m[b * KHID + k];
    }
    __syncthreads();
    const int jj = tid & 63, ks = tid >> 6;
    float ap = 0.f, am = 0.f;
    const float* wp = w2 + j0 + jj;
    #pragma unroll 4
    for (int k = ks * 128; k < ks * 128 + 128; k++) {
        float w = wp[(long long)k * ND];
        ap += up[k] * w;
        am += um[k] * w;
    }
    sap[ks][jj] = ap; sam[ks][jj] = am;
    __syncthreads();
    if (ks == 0) {
        float a = sap[0][jj] + sap[1][jj] + sap[2][jj] + sap[3][jj];
        float m = sam[0][jj] + sam[1][jj] + sam[2][jj] + sam[3][jj];
        float pa = g_scal[b * 4 + 0], cpv = g_scal[b * 4 + 1], cmv = g_scal[b * 4 + 2];
        float val = pa * (cpv * a - cmv * m);
        g_struct[b * ND + j0 + jj] = val > 0.f ? val : 0.2f * val;
    }
}

// ===== Kernel D: fused  hs-copy (+struct on row 0)  and  selected-gather =======
#define N1F4 (NB * NNtok * (ND / 4))
__global__ __launch_bounds__(256) void kOut(const float4* __restrict__ hin,
                                            float4* __restrict__ out,
                                            int seln, int ntot)
{
    int i = blockIdx.x * 256 + threadIdx.x;
    if (i >= ntot) return;
    if (i < N1F4) {
        float4 v = hin[i];
        int row = i / (ND / 4);
        if (row % NNtok == 0) {
            int b = row / NNtok;
            int d = (i % (ND / 4)) * 4;
            const float* st = &g_struct[b * ND + d];
            v.x += st[0]; v.y += st[1]; v.z += st[2]; v.w += st[3];
        }
        out[i] = v;
    } else {
        int k = i - N1F4;
        int row = k / (ND / 4), d4 = k % (ND / 4);
        int b = row / seln, q = row % seln;
        int p = g_patch[b * NS + q];     // in [1,784] -> unmodified hs rows
        out[i] = hin[(long long)(b * NNtok + p) * (ND / 4) + d4];
    }
}

// ---------------- launch ----------------
extern "C" void kernel_launch(void* const* d_in, const int* in_sizes, int n_in,
                              void* d_out, int out_size)
{
    const float* hs = (const float*)d_in[0];
    const float* x  = (const float*)d_in[1];
    const float* w1 = (const float*)d_in[2];
    const float* w2 = (const float*)d_in[3];

    const int hs_elems = NB * NNtok * ND;
    int seln = (out_size - hs_elems) / (NB * ND);
    if (seln < 1) seln = 1;

    kTopSel<<<NB * NC, 256>>>(x);
    kPerB<<<NB, 256>>>(w1, seln);
    kStruct<<<NB * 12, 256>>>(w2);
    int ntot = N1F4 + NB * seln * (ND / 4);
    kOut<<<(ntot + 255) / 256, 256>>>((const float4*)hs, (float4*)d_out, seln, ntot);
}

// round 4
// speedup vs baseline: 1.8937x; 1.2403x over previous
#include <cuda_runtime.h>
#include <math.h>

#define NB 8
#define NC 12
#define NNtok 785
#define NS 784
#define NH 28
#define ND 768
#define KHID 512
#define PNUM 84
#define SCL 0.7f

// ---------------- device scratch ----------------
__device__ float         g_ns[NB * NC * NS];   // new_score
__device__ unsigned char g_sel[NB * NC * NS];  // selected flag per (b,c,s)
__device__ float         g_u1p[NB * KHID];     // relu(u1)
__device__ float         g_u1m[NB * KHID];     // relu(-u1)
__device__ float         g_scal[NB * 4];       // pw[anchor], c+, c-
__device__ int           g_patch[NB * NS];     // patch idx by rank (first seln used)

// ================= Kernel A: per (b,c) top-84 via 4-pass radix select ==========
__global__ __launch_bounds__(256) void kTopSel(const float* __restrict__ x)
{
    __shared__ float    sc[NS];
    __shared__ unsigned su[NS];
    __shared__ int      hist[256];
    __shared__ int      wpre[8];
    __shared__ unsigned s_pref;
    __shared__ int      s_rem;
    const int bc = blockIdx.x, tid = threadIdx.x;
    const int warp = tid >> 5, lane = tid & 31;
    const float* row = x + (long long)bc * NNtok * NNtok + 1;   // x[b,c,0,1:]

    for (int i = tid; i < NS; i += 256) {
        float v = row[i];
        sc[i] = v;
        unsigned ub = __float_as_uint(v);
        su[i] = (ub & 0x80000000u) ? ~ub : (ub | 0x80000000u);  // order-preserving key
    }
    if (tid == 0) { s_pref = 0u; s_rem = PNUM; }
    __syncthreads();

    #pragma unroll
    for (int pass = 0; pass < 4; pass++) {
        const int shift = 24 - 8 * pass;
        const unsigned mask_hi = (pass == 0) ? 0u : (0xFFFFFFFFu << (shift + 8));
        const unsigned pref = s_pref;
        const int rem = s_rem;
        hist[tid] = 0;
        __syncthreads();
        for (int i = tid; i < NS; i += 256) {
            unsigned u = su[i];
            if ((u & mask_hi) == pref) atomicAdd(&hist[(u >> shift) & 0xFFu], 1);
        }
        __syncthreads();
        // fast suffix count via warp scan: gt(v) = total - inclusive_prefix(v)
        const int h = hist[tid];
        int s = h;
        #pragma unroll
        for (int o = 1; o < 32; o <<= 1) {
            int n = __shfl_up_sync(0xFFFFFFFFu, s, o);
            if (lane >= o) s += n;
        }
        if (lane == 31) wpre[warp] = s;
        __syncthreads();
        int off = 0, total = 0;
        #pragma unroll
        for (int r = 0; r < 8; r++) { int w = wpre[r]; total += w; if (r < warp) off += w; }
        const int gt = total - (s + off);     // # keys strictly greater than bin tid
        if (gt < rem && gt + h >= rem) {
            s_pref = pref | ((unsigned)tid << shift);
            s_rem  = rem - gt;
        }
        __syncthreads();
    }
    const unsigned T = s_pref;   // exact 84th-largest key
    const int need  = s_rem;     // # of T-ties to take (ascending index = lax.top_k)

    for (int i = tid; i < NS; i += 256) {
        unsigned u = su[i];
        bool sel;
        if (u > T) sel = true;
        else if (u == T) {
            int e = 0;
            for (int j = 0; j < i; j++) e += (su[j] == T) ? 1 : 0;
            sel = (e < need);
        } else sel = false;
        g_ns[bc * NS + i]  = sel ? sc[i] : sc[i] * SCL;
        g_sel[bc * NS + i] = sel ? (unsigned char)1 : (unsigned char)0;
    }
}

// ===== Kernel B: per-b stats + anchor + u1 + count-conv + stable ranks =========
__global__ __launch_bounds__(256) void kPerB(const float* __restrict__ w1, int seln)
{
    __shared__ float msh[NS];
    __shared__ int   c0[NS];
    __shared__ int   cc[NS];
    __shared__ int   whist[8][256];
    __shared__ int   sfx[256];
    __shared__ float redf[8], redf2[8], redf3[8], redf4[8];
    __shared__ int   redi[8];
    __shared__ float s_mean, s_w0, s_w1;
    __shared__ int   s_anchor;
    const int b = blockIdx.x, tid = threadIdx.x;
    const int warp = tid >> 5, lane = tid & 31;

    // ---- m[s] = sum_c new_score; mean ----
    float psum = 0.f;
    for (int s = tid; s < NS; s += 256) {
        float m = 0.f;
        #pragma unroll
        for (int c = 0; c < NC; c++) m += g_ns[(b * NC + c) * NS + s];
        msh[s] = m;
        psum += m;
    }
    for (int o = 16; o; o >>= 1) psum += __shfl_xor_sync(0xFFFFFFFFu, psum, o);
    if (lane == 0) redf[warp] = psum;
    __syncthreads();
    if (tid == 0) {
        float t = 0.f; for (int w = 0; w < 8; w++) t += redf[w];
        s_mean = t / (float)NS;
    }
    __syncthreads();
    const float mean = s_mean;

    // ---- anchor = argmax(binary * m / C), first-index tie-break ----
    float bv = -1e30f; int bi = NS;
    for (int s = tid; s < NS; s += 256) {
        float m = msh[s];
        float v = (m > mean) ? m * (1.0f / NC) : 0.0f;
        if (v > bv || (v == bv && s < bi)) { bv = v; bi = s; }
    }
    for (int o = 16; o; o >>= 1) {
        float ov = __shfl_xor_sync(0xFFFFFFFFu, bv, o);
        int   oi = __shfl_xor_sync(0xFFFFFFFFu, bi, o);
        if (ov > bv || (ov == bv && oi < bi)) { bv = ov; bi = oi; }
    }
    if (lane == 0) { redf[warp] = bv; redi[warp] = bi; }
    __syncthreads();
    if (tid == 0) {
        float v = redf[0]; int i = redi[0];
        for (int w = 1; w < 8; w++)
            if (redf[w] > v || (redf[w] == v && redi[w] < i)) { v = redf[w]; i = redi[w]; }
        s_anchor = i;
    }
    __syncthreads();
    const int anchor = s_anchor;
    const float ai = (float)(anchor / NH), aj = (float)(anchor % NH);

    // ---- w0 = sum pw*dist, w1 = sum pw*ang, c± = sum pw^2 by sign ----
    float w0 = 0.f, w1s = 0.f, cpv = 0.f, cmv = 0.f;
    for (int s = tid; s < NS; s += 256) {
        float p   = msh[s] * (1.0f / NC);
        float rc0 = ((float)(s / NH) - ai) / (float)NH;
        float rc1 = ((float)(s % NH) - aj) / (float)NH;
        float dist = sqrtf(rc0 * rc0 + rc1 * rc1);
        float ang  = (atan2f(rc1, rc0) * 0.3183098861837907f + 1.0f) * 0.5f;
        w0  += p * dist;
        w1s += p * ang;
        if (p > 0.f) cpv += p * p; else if (p < 0.f) cmv += p * p;
    }
    for (int o = 16; o; o >>= 1) {
        w0  += __shfl_xor_sync(0xFFFFFFFFu, w0,  o);
        w1s += __shfl_xor_sync(0xFFFFFFFFu, w1s, o);
        cpv += __shfl_xor_sync(0xFFFFFFFFu, cpv, o);
        cmv += __shfl_xor_sync(0xFFFFFFFFu, cmv, o);
    }
    if (lane == 0) { redf[warp] = w0; redf2[warp] = w1s; redf3[warp] = cpv; redf4[warp] = cmv; }
    __syncthreads();
    if (tid == 0) {
        float a = 0, bb = 0, c = 0, d = 0;
        for (int w = 0; w < 8; w++) { a += redf[w]; bb += redf2[w]; c += redf3[w]; d += redf4[w]; }
        s_w0 = a; s_w1 = bb;
        g_scal[b * 4 + 0] = msh[anchor] * (1.0f / NC);
        g_scal[b * 4 + 1] = c;
        g_scal[b * 4 + 2] = d;
    }
    __syncthreads();

    // ---- u1 halves ----
    {
        const float W0 = s_w0, W1v = s_w1;
        for (int k = tid; k < KHID; k += 256) {
            float u = W0 * w1[k] + W1v * w1[KHID + k];
            g_u1p[b * KHID + k] = fmaxf(u, 0.f);
            g_u1m[b * KHID + k] = fmaxf(-u, 0.f);
        }
    }

    // ---- count = sum_c selmask ----
    for (int s = tid; s < NS; s += 256) {
        int t = 0;
        #pragma unroll
        for (int c = 0; c < NC; c++) t += (int)g_sel[(b * NC + c) * NS + s];
        c0[s] = t;
    }
    #pragma unroll
    for (int r = 0; r < 8; r++) whist[r][tid] = 0;
    __syncthreads();

    // ---- 3x3 conv + per-warp (98-elem chunk) value histograms ----
    {
        const int base = warp * 98;                 // 8*98 = 784 exactly
        for (int o = lane; o < 98; o += 32) {
            int s = base + o;
            int i0 = s / NH, j0 = s % NH;
            int acc = 0;
            #pragma unroll
            for (int di = -1; di <= 1; di++)
                #pragma unroll
                for (int dj = -1; dj <= 1; dj++) {
                    int ii = i0 + di, jj = j0 + dj;
                    if (ii >= 0 && ii < NH && jj >= 0 && jj < NH)
                        acc += (2 - abs(di)) * (2 - abs(dj)) * c0[ii * NH + jj];
                }
            cc[s] = acc;                            // max 192 < 256
            atomicAdd(&whist[warp][acc], 1);
        }
    }
    __syncthreads();
    {   // sfx[v] = # strictly greater, via warp scan
        int h = 0;
        #pragma unroll
        for (int r = 0; r < 8; r++) h += whist[r][tid];
        int s = h;
        #pragma unroll
        for (int o = 1; o < 32; o <<= 1) {
            int n = __shfl_up_sync(0xFFFFFFFFu, s, o);
            if (lane >= o) s += n;
        }
        if (lane == 31) redi[warp] = s;
        __syncthreads();
        int off = 0, total = 0;
        #pragma unroll
        for (int r = 0; r < 8; r++) { int w = redi[r]; total += w; if (r < warp) off += w; }
        sfx[tid] = total - (s + off);
    }
    __syncthreads();

    // ---- stable descending rank, write patch indices ----
    {
        const int base = warp * 98;
        for (int o = lane; o < 98; o += 32) {
            int i = base + o;
            int v = cc[i];
            int g = sfx[v];
            if (g < seln) {
                int e = 0;
                #pragma unroll
                for (int r = 0; r < 8; r++) if (r < warp) e += whist[r][v];
                for (int j = base; j < i; j++) e += (cc[j] == v) ? 1 : 0;
                int rk = g + e;                     // ties by ascending index (stable)
                if (rk < seln) g_patch[b * NS + rk] = i + 1;
            }
        }
    }
}

// ===== Kernel C: fused struct-GEMV(+row0 write), hs copy, selected gather ======
#define SBLK 96
#define NCOPY4 (NB * NS * (ND / 4))          // 1,204,224 float4 (rows 1..784)
#define CBLK (NCOPY4 / 1024)                  // 1176 blocks, 4 float4/thread
__global__ __launch_bounds__(256) void kFinal(const float* __restrict__ w2,
                                              const float4* __restrict__ hin,
                                              float4* __restrict__ out,
                                              int seln, int ngat4)
{
    const int bi = blockIdx.x, tid = threadIdx.x;

    if (bi < SBLK) {
        // ---- struct row @ anchor:  leaky(pw_a*(c+ * (u1p@W2) - c- * (u1m@W2))) ----
        __shared__ float up[KHID], um[KHID];
        __shared__ float sap[4][64], sam[4][64];
        const int b  = bi / 12;
        const int j0 = (bi % 12) * 64;
        for (int k = tid; k < KHID; k += 256) {
            up[k] = g_u1p[b * KHID + k];
            um[k] = g_u1m[b * KHID + k];
        }
        __syncthreads();
        const int jj = tid & 63, ks = tid >> 6;
        float ap = 0.f, am = 0.f;
        const float* wp = w2 + j0 + jj;
        #pragma unroll 4
        for (int k = ks * 128; k < ks * 128 + 128; k++) {
            float w = wp[(long long)k * ND];
            ap += up[k] * w;
            am += um[k] * w;
        }
        sap[ks][jj] = ap; sam[ks][jj] = am;
        __syncthreads();
        if (ks == 0) {
            float a = sap[0][jj] + sap[1][jj] + sap[2][jj] + sap[3][jj];
            float m = sam[0][jj] + sam[1][jj] + sam[2][jj] + sam[3][jj];
            float pa = g_scal[b * 4 + 0], cpv = g_scal[b * 4 + 1], cmv = g_scal[b * 4 + 2];
            float val = pa * (cpv * a - cmv * m);
            val = val > 0.f ? val : 0.2f * val;
            const int fi = (b * NNtok) * ND + j0 + jj;          // row 0 of batch b
            ((float*)out)[fi] = ((const float*)hin)[fi] + val;
        }
    } else if (bi < SBLK + CBLK) {
        // ---- hs rows 1..784 copy: 4 float4 per thread, block-strided ----
        const int base = (bi - SBLK) * 1024 + tid;
        float4 v[4];
        int oi[4];
        #pragma unroll
        for (int j = 0; j < 4; j++) {
            int k  = base + j * 256;                 // (b, n, d4) over NB*NS*192
            int b  = k / (NS * (ND / 4));
            int r  = k - b * (NS * (ND / 4));
            int n  = r / (ND / 4);
            int d4 = r - n * (ND / 4);
            int idx = (b * NNtok + n + 1) * (ND / 4) + d4;
            v[j]  = hin[idx];
            oi[j] = idx;
        }
        #pragma unroll
        for (int j = 0; j < 4; j++) out[oi[j]] = v[j];
    } else {
        // ---- selected gather: 4 float4 per thread ----
        const int base = (bi - SBLK - CBLK) * 1024 + tid;
        #pragma unroll
        for (int j = 0; j < 4; j++) {
            int k = base + j * 256;
            if (k < ngat4) {
                int row = k / (ND / 4), d4 = k - row * (ND / 4);
                int b = row / seln, q = row - b * seln;
                int p = g_patch[b * NS + q];         // in [1,784]: unmodified hs rows
                out[NB * NNtok * (ND / 4) + k] = hin[(b * NNtok + p) * (ND / 4) + d4];
            }
        }
    }
}

// ---------------- launch ----------------
extern "C" void kernel_launch(void* const* d_in, const int* in_sizes, int n_in,
                              void* d_out, int out_size)
{
    const float* hs = (const float*)d_in[0];
    const float* x  = (const float*)d_in[1];
    const float* w1 = (const float*)d_in[2];
    const float* w2 = (const float*)d_in[3];

    const int hs_elems = NB * NNtok * ND;
    int seln = (out_size - hs_elems) / (NB * ND);
    if (seln < 1) seln = 1;

    kTopSel<<<NB * NC, 256>>>(x);
    kPerB<<<NB, 256>>>(w1, seln);
    int ngat4 = NB * seln * (ND / 4);
    int gblk  = (ngat4 + 1023) / 1024;
    kFinal<<<SBLK + CBLK + gblk, 256>>>(w2, (const float4*)hs, (float4*)d_out,
                                        seln, ngat4);
}

// round 5
// speedup vs baseline: 2.2945x; 1.2116x over previous
#include <cuda_runtime.h>
#include <math.h>

#define NB 8
#define NC 12
#define NNtok 785
#define NS 784
#define NH 28
#define ND 768
#define KHID 512
#define PNUM 84
#define SCL 0.7f
#define NT 800          // 25 warps; thread tid<784 owns element tid
#define NW 25

// ---------------- device scratch ----------------
__device__ float         g_ns[NB * NC * NS];
__device__ unsigned char g_sel[NB * NC * NS];
__device__ float         g_u1p[NB * KHID];
__device__ float         g_u1m[NB * KHID];
__device__ float         g_scal[NB * 4];
__device__ int           g_patch[NB * NS];

// ================= Kernel A: per (b,c) top-84 via 4-pass radix select ==========
__global__ __launch_bounds__(NT) void kTopSel(const float* __restrict__ x)
{
    __shared__ unsigned su[NS];
    __shared__ int      hist[256];
    __shared__ int      wpre[8];
    __shared__ unsigned s_pref;
    __shared__ int      s_rem;
    const int bc = blockIdx.x, tid = threadIdx.x;
    const int lane = tid & 31;
    const bool act = (tid < NS);

    float    myv = 0.f;
    unsigned myu = 0u;
    if (act) {
        myv = x[(long long)bc * NNtok * NNtok + 1 + tid];   // x[b,c,0,1+tid]
        unsigned ub = __float_as_uint(myv);
        myu = (ub & 0x80000000u) ? ~ub : (ub | 0x80000000u);
        su[tid] = myu;
    }
    if (tid == 0) { s_pref = 0u; s_rem = PNUM; }
    __syncthreads();

    #pragma unroll
    for (int pass = 0; pass < 4; pass++) {
        const int shift = 24 - 8 * pass;
        const unsigned mask_hi = (pass == 0) ? 0u : (0xFFFFFFFFu << (shift + 8));
        const unsigned pref = s_pref;
        const int rem = s_rem;
        if (tid < 256) hist[tid] = 0;
        __syncthreads();
        if (act && (myu & mask_hi) == pref)
            atomicAdd(&hist[(myu >> shift) & 0xFFu], 1);
        __syncthreads();
        if (tid < 256) {
            const int h = hist[tid];
            int s = h;
            #pragma unroll
            for (int o = 1; o < 32; o <<= 1) {
                int n = __shfl_up_sync(0xFFFFFFFFu, s, o);
                if (lane >= o) s += n;
            }
            if (lane == 31) wpre[tid >> 5] = s;
            __syncthreads();
            int off = 0, total = 0;
            #pragma unroll
            for (int r = 0; r < 8; r++) {
                int w = wpre[r]; total += w; if (r < (tid >> 5)) off += w;
            }
            const int gt = total - (s + off);   // # keys strictly greater than bin
            if (gt < rem && gt + h >= rem) {
                s_pref = pref | ((unsigned)tid << shift);
                s_rem  = rem - gt;
            }
        } else {
            __syncthreads();
        }
        __syncthreads();
    }
    const unsigned T = s_pref;      // exact 84th-largest key
    const int need  = s_rem;        // ties taken ascending-index (= lax.top_k)

    if (act) {
        bool sel;
        if (myu > T) sel = true;
        else if (myu == T) {
            int e = 0;
            for (int j = 0; j < tid; j++) e += (su[j] == T) ? 1 : 0;  // rare
            sel = (e < need);
        } else sel = false;
        g_ns[bc * NS + tid]  = sel ? myv : myv * SCL;
        g_sel[bc * NS + tid] = sel ? (unsigned char)1 : (unsigned char)0;
    }
}

// ===== Kernel B: per-b stats + anchor + u1 + count-conv + stable ranks =========
__global__ __launch_bounds__(NT) void kPerB(const float* __restrict__ w1, int seln)
{
    __shared__ float msh[NS];
    __shared__ int   c0[NS];
    __shared__ int   whist[NW][256];
    __shared__ int   sfx[256];
    __shared__ float redf[NW], redf2[NW], redf3[NW], redf4[NW];
    __shared__ int   redi[NW], redw[8];
    __shared__ float s_mean, s_w0, s_w1;
    __shared__ int   s_anchor;
    const int b = blockIdx.x, tid = threadIdx.x;
    const int warp = tid >> 5, lane = tid & 31;
    const bool act = (tid < NS);

    // ---- m[s] = sum_c new_score; mean ----
    float m = 0.f;
    if (act) {
        #pragma unroll
        for (int c = 0; c < NC; c++) m += g_ns[(b * NC + c) * NS + tid];
        msh[tid] = m;
    }
    float psum = act ? m : 0.f;
    for (int o = 16; o; o >>= 1) psum += __shfl_xor_sync(0xFFFFFFFFu, psum, o);
    if (lane == 0) redf[warp] = psum;
    __syncthreads();
    if (tid == 0) {
        float t = 0.f;
        for (int w = 0; w < NW; w++) t += redf[w];
        s_mean = t / (float)NS;
    }
    __syncthreads();
    const float mean = s_mean;

    // ---- anchor = argmax(binary*m/C), first-index tie-break ----
    float bv = -1e30f; int bi = NS;
    if (act) {
        float v = (m > mean) ? m * (1.0f / NC) : 0.0f;
        bv = v; bi = tid;
    }
    for (int o = 16; o; o >>= 1) {
        float ov = __shfl_xor_sync(0xFFFFFFFFu, bv, o);
        int   oi = __shfl_xor_sync(0xFFFFFFFFu, bi, o);
        if (ov > bv || (ov == bv && oi < bi)) { bv = ov; bi = oi; }
    }
    if (lane == 0) { redf[warp] = bv; redi[warp] = bi; }
    __syncthreads();
    if (tid == 0) {
        float v = redf[0]; int i = redi[0];
        for (int w = 1; w < NW; w++)
            if (redf[w] > v || (redf[w] == v && redi[w] < i)) { v = redf[w]; i = redi[w]; }
        s_anchor = i;
    }
    __syncthreads();
    const int anchor = s_anchor;
    const float ai = (float)(anchor / NH), aj = (float)(anchor % NH);

    // ---- w0 = Σ pw·dist, w1 = Σ pw·ang, c± = Σ pw² by sign ----
    float w0 = 0.f, w1s = 0.f, cpv = 0.f, cmv = 0.f;
    if (act) {
        float p   = m * (1.0f / NC);
        float rc0 = ((float)(tid / NH) - ai) / (float)NH;
        float rc1 = ((float)(tid % NH) - aj) / (float)NH;
        w0  = p * sqrtf(rc0 * rc0 + rc1 * rc1);
        w1s = p * (atan2f(rc1, rc0) * 0.3183098861837907f + 1.0f) * 0.5f;
        if (p > 0.f) cpv = p * p; else if (p < 0.f) cmv = p * p;
    }
    for (int o = 16; o; o >>= 1) {
        w0  += __shfl_xor_sync(0xFFFFFFFFu, w0,  o);
        w1s += __shfl_xor_sync(0xFFFFFFFFu, w1s, o);
        cpv += __shfl_xor_sync(0xFFFFFFFFu, cpv, o);
        cmv += __shfl_xor_sync(0xFFFFFFFFu, cmv, o);
    }
    if (lane == 0) { redf[warp] = w0; redf2[warp] = w1s; redf3[warp] = cpv; redf4[warp] = cmv; }
    __syncthreads();
    if (tid == 0) {
        float a = 0, bb = 0, c = 0, d = 0;
        for (int w = 0; w < NW; w++) { a += redf[w]; bb += redf2[w]; c += redf3[w]; d += redf4[w]; }
        s_w0 = a; s_w1 = bb;
        g_scal[b * 4 + 0] = msh[anchor] * (1.0f / NC);
        g_scal[b * 4 + 1] = c;
        g_scal[b * 4 + 2] = d;
    }

    // ---- count c0 + zero whist (no dependence on scalars above) ----
    if (act) {
        int t = 0;
        #pragma unroll
        for (int c = 0; c < NC; c++) t += (int)g_sel[(b * NC + c) * NS + tid];
        c0[tid] = t;
    }
    for (int i = tid; i < NW * 256; i += NT) ((int*)whist)[i] = 0;
    __syncthreads();

    // ---- u1 halves ----
    if (tid < KHID) {
        float u = s_w0 * w1[tid] + s_w1 * w1[KHID + tid];
        g_u1p[b * KHID + tid] = fmaxf(u, 0.f);
        g_u1m[b * KHID + tid] = fmaxf(-u, 0.f);
    }

    // ---- 3x3 conv + per-warp value histogram (warp w owns s = w*32+lane) ----
    int vcc = 0;
    if (act) {
        int i0 = tid / NH, j0 = tid % NH;
        #pragma unroll
        for (int di = -1; di <= 1; di++)
            #pragma unroll
            for (int dj = -1; dj <= 1; dj++) {
                int ii = i0 + di, jj = j0 + dj;
                if (ii >= 0 && ii < NH && jj >= 0 && jj < NH)
                    vcc += (2 - abs(di)) * (2 - abs(dj)) * c0[ii * NH + jj];
            }
        atomicAdd(&whist[warp][vcc], 1);     // vcc in [0,192]
    }
    __syncthreads();

    // ---- sfx[v] = # strictly greater (warp-scan suffix over 256 bins) ----
    if (tid < 256) {
        int h = 0;
        #pragma unroll
        for (int r = 0; r < NW; r++) h += whist[r][tid];
        int s = h;
        #pragma unroll
        for (int o = 1; o < 32; o <<= 1) {
            int n = __shfl_up_sync(0xFFFFFFFFu, s, o);
            if (lane >= o) s += n;
        }
        if (lane == 31) redw[tid >> 5] = s;
        __syncthreads();
        int off = 0, total = 0;
        #pragma unroll
        for (int r = 0; r < 8; r++) {
            int w = redw[r]; total += w; if (r < (tid >> 5)) off += w;
        }
        sfx[tid] = total - (s + off);
    } else {
        __syncthreads();
    }
    __syncthreads();

    // ---- stable descending rank via match_any (no scan loops) ----
    if (act) {
        const unsigned wmask = (warp == NW - 1) ? 0xFFFFu : 0xFFFFFFFFu;
        unsigned mmask = __match_any_sync(wmask, vcc);
        int g = sfx[vcc];
        if (g < seln) {
            int e = __popc(mmask & ((1u << lane) - 1u));
            for (int r = 0; r < warp; r++) e += whist[r][vcc];
            int rk = g + e;                 // ties by ascending index (stable)
            if (rk < seln) g_patch[b * NS + rk] = tid + 1;
        }
    }
}

// ===== Kernel C: fused struct-GEMV(+row0 write), hs copy, selected gather ======
#define SBLK 96
#define NCOPY4 (NB * NS * (ND / 4))           // 1,204,224 float4 (rows 1..784)
#define CBLK (NCOPY4 / 2048)                  // 588 blocks, 8 float4/thread
__global__ __launch_bounds__(256) void kFinal(const float* __restrict__ w2,
                                              const float4* __restrict__ hin,
                                              float4* __restrict__ out,
                                              int seln, int ngat4)
{
    const int bi = blockIdx.x, tid = threadIdx.x;

    if (bi < SBLK) {
        // ---- struct row @ anchor: leaky(pw_a*(c+·(u1p@W2) − c−·(u1m@W2))) ----
        __shared__ float up[KHID], um[KHID];
        __shared__ float sap[4][64], sam[4][64];
        const int b  = bi / 12;
        const int j0 = (bi % 12) * 64;
        for (int k = tid; k < KHID; k += 256) {
            up[k] = g_u1p[b * KHID + k];
            um[k] = g_u1m[b * KHID + k];
        }
        __syncthreads();
        const int jj = tid & 63, ks = tid >> 6;
        float ap = 0.f, am = 0.f;
        const float* wp = w2 + j0 + jj;
        #pragma unroll 4
        for (int k = ks * 128; k < ks * 128 + 128; k++) {
            float w = wp[(long long)k * ND];
            ap += up[k] * w;
            am += um[k] * w;
        }
        sap[ks][jj] = ap; sam[ks][jj] = am;
        __syncthreads();
        if (ks == 0) {
            float a = sap[0][jj] + sap[1][jj] + sap[2][jj] + sap[3][jj];
            float mm = sam[0][jj] + sam[1][jj] + sam[2][jj] + sam[3][jj];
            float pa = g_scal[b * 4 + 0], cpv = g_scal[b * 4 + 1], cmv = g_scal[b * 4 + 2];
            float val = pa * (cpv * a - cmv * mm);
            val = val > 0.f ? val : 0.2f * val;
            const int fi = (b * NNtok) * ND + j0 + jj;          // row 0 of batch b
            ((float*)out)[fi] = ((const float*)hin)[fi] + val;
        }
    } else if (bi < SBLK + CBLK) {
        // ---- hs rows 1..784 copy: 8 float4/thread, block-strided (MLP 8) ----
        const int base = (bi - SBLK) * 2048 + tid;
        float4 v[8];
        int oi[8];
        #pragma unroll
        for (int j = 0; j < 8; j++) {
            int k  = base + j * 256;
            int b  = k / (NS * (ND / 4));
            int r  = k - b * (NS * (ND / 4));
            int n  = r / (ND / 4);
            int d4 = r - n * (ND / 4);
            int idx = (b * NNtok + n + 1) * (ND / 4) + d4;
            v[j]  = hin[idx];
            oi[j] = idx;
        }
        #pragma unroll
        for (int j = 0; j < 8; j++) out[oi[j]] = v[j];
    } else {
        // ---- selected gather: 4 float4/thread ----
        const int base = (bi - SBLK - CBLK) * 1024 + tid;
        #pragma unroll
        for (int j = 0; j < 4; j++) {
            int k = base + j * 256;
            if (k < ngat4) {
                int row = k / (ND / 4), d4 = k - row * (ND / 4);
                int b = row / seln, q = row - b * seln;
                int p = g_patch[b * NS + q];     // in [1,784]: unmodified hs rows
                out[NB * NNtok * (ND / 4) + k] = hin[(b * NNtok + p) * (ND / 4) + d4];
            }
        }
    }
}

// ---------------- launch ----------------
extern "C" void kernel_launch(void* const* d_in, const int* in_sizes, int n_in,
                              void* d_out, int out_size)
{
    const float* hs = (const float*)d_in[0];
    const float* x  = (const float*)d_in[1];
    const float* w1 = (const float*)d_in[2];
    const float* w2 = (const float*)d_in[3];

    const int hs_elems = NB * NNtok * ND;
    int seln = (out_size - hs_elems) / (NB * ND);
    if (seln < 1) seln = 1;

    kTopSel<<<NB * NC, NT>>>(x);
    kPerB<<<NB, NT>>>(w1, seln);
    int ngat4 = NB * seln * (ND / 4);
    int gblk  = (ngat4 + 1023) / 1024;
    kFinal<<<SBLK + CBLK + gblk, 256>>>(w2, (const float4*)hs, (float4*)d_out,
                                        seln, ngat4);
}